// round 14
// baseline (speedup 1.0000x reference)
#include <cuda_runtime.h>
#include <cuda_bf16.h>
#include <math.h>
#include <stdint.h>

#define N_E     8192
#define C_DIM   256
#define BATCH   32
#define HW      1024
#define N_ROWS  (BATCH * HW)            // 32768
#define ZQ_ELEMS (BATCH * C_DIM * HW)   // 8388608

#define BM      128                     // rows per CTA
#define KW      512                     // W row: [hi(256) | lo(256)]
#define NETILE  64                      // e-tiles of 128 codes
#define NITER   (NETILE * 4)            // 256 chunk iterations
#define NRT     (N_ROWS / BM)           // 256 row tiles

// smem offsets (dynamic)
#define A_HI   0                        // [256 k][128 m] bf16 swizzled (64KB)
#define A_LO   65536                    // (64KB)
#define W_OFF  131072                   // 3-stage ring of 32KB chunks
#define CHUNK_BYTES 32768
#define SRED   131072                   // alias of W ring (post-GEMM)
#define SMEM_BYTES (131072 + 3 * CHUNK_BYTES)   // 229376

// prep kernel block ranges (W hi/lo split + znorm + zero; no transpose)
#define PREP_WPREP_BLOCKS 2048
#define PREP_ZNORM_BLOCKS (N_ROWS / 256)        // 128
#define PREP_ZERO_BLOCKS  (N_E / 256)           // 32
#define PREP_BLOCKS (PREP_WPREP_BLOCKS + PREP_ZNORM_BLOCKS + PREP_ZERO_BLOCKS)

// epilogue: 4 channel-quarters per row tile
#define EPI_BLOCKS (NRT * 4)            // 1024

// ---- scratch (no allocations allowed) ----
__device__ __align__(16) __nv_bfloat16 g_Wb[N_E * KW];    // [e][hi|lo]  8.4MB
__device__ float  g_znorm[N_ROWS];
__device__ int    g_idx[N_ROWS];
__device__ int    g_hist[N_E];
__device__ double g_loss;
__device__ unsigned g_done;

// =========================== helpers ===================================
__device__ __forceinline__ uint32_t smem_u32(const void* p) {
    uint32_t a;
    asm("{ .reg .u64 t; cvta.to.shared.u64 t, %1; cvt.u32.u64 %0, t; }" : "=r"(a) : "l"(p));
    return a;
}
__device__ __forceinline__ void ldsm4(uint32_t* r, uint32_t addr) {
    asm volatile("ldmatrix.sync.aligned.m8n8.x4.shared.b16 {%0,%1,%2,%3}, [%4];"
                 : "=r"(r[0]), "=r"(r[1]), "=r"(r[2]), "=r"(r[3]) : "r"(addr));
}
__device__ __forceinline__ void ldsm4t(uint32_t* r, uint32_t addr) {
    asm volatile("ldmatrix.sync.aligned.m8n8.x4.trans.shared.b16 {%0,%1,%2,%3}, [%4];"
                 : "=r"(r[0]), "=r"(r[1]), "=r"(r[2]), "=r"(r[3]) : "r"(addr));
}
__device__ __forceinline__ void mma16816(float* d, const uint32_t* a, const uint32_t* b) {
    asm volatile("mma.sync.aligned.m16n8k16.row.col.f32.bf16.bf16.f32 "
                 "{%0,%1,%2,%3}, {%4,%5,%6,%7}, {%8,%9}, {%0,%1,%2,%3};"
                 : "+f"(d[0]), "+f"(d[1]), "+f"(d[2]), "+f"(d[3])
                 : "r"(a[0]), "r"(a[1]), "r"(a[2]), "r"(a[3]), "r"(b[0]), "r"(b[1]));
}
__device__ __forceinline__ void cp16(uint32_t dst, const void* src) {
    asm volatile("cp.async.cg.shared.global [%0], [%1], 16;" :: "r"(dst), "l"(src));
}
#define CP_COMMIT() asm volatile("cp.async.commit_group;" ::: "memory")
#define CP_WAIT1()  asm volatile("cp.async.wait_group 1;"  ::: "memory")

// ===========================================================================
// 1) fused prep: W hi/lo split, znorm, zero.  All independent block ranges.
// ===========================================================================
__global__ void k_prep(const float* __restrict__ W, const float* __restrict__ z) {
    int bid = blockIdx.x;
    int tid = threadIdx.x;
    if (bid < PREP_WPREP_BLOCKS) {
        int e0 = (bid & 255) * 32, k0 = (bid >> 8) * 32;
        int tx = tid & 31, ty = tid >> 5;
        #pragma unroll
        for (int j = 0; j < 4; j++) {
            int e = e0 + ty + 8 * j;
            int k = k0 + tx;
            float w = W[(size_t)e * C_DIM + k];
            __nv_bfloat16 hi = __float2bfloat16_rn(w);
            __nv_bfloat16 lo = __float2bfloat16_rn(w - __bfloat162float(hi));
            size_t base = (size_t)e * KW;
            g_Wb[base + k]       = hi;
            g_Wb[base + 256 + k] = lo;
        }
    } else if (bid < PREP_WPREP_BLOCKS + PREP_ZNORM_BLOCKS) {
        // |z_n|^2 — identical accumulation order since R2 (sets score bins)
        int n = (bid - PREP_WPREP_BLOCKS) * 256 + tid;
        int b = n >> 10, hw = n & 1023;
        const float* p = z + (size_t)b * C_DIM * HW + hw;
        float s = 0.f;
        #pragma unroll 8
        for (int c = 0; c < C_DIM; c++) { float v = p[(size_t)c * HW]; s += v * v; }
        g_znorm[n] = s;
    } else {
        int i = (bid - PREP_WPREP_BLOCKS - PREP_ZNORM_BLOCKS) * 256 + tid;
        if (i < N_E) g_hist[i] = 0;
        if (i == 0)  { g_loss = 0.0; g_done = 0u; }
    }
}

// ===========================================================================
// 2) main: bf16 HMMA argmin — BYTE-IDENTICAL to R13 (grid 256, 256 thr).
//    score = fl(|z|^2 - 2*(z.w));  dot = hi.hi + lo.hi + hi.lo  (3 passes)
// ===========================================================================
__global__ __launch_bounds__(256, 1)
void k_argmin_mma(const float* __restrict__ z) {
    extern __shared__ char smem[];
    const uint32_t SB = smem_u32(smem);
    int tid = threadIdx.x;
    int L = tid & 31, wid = tid >> 5;
    int mw = wid >> 2, nw = wid & 3;            // warp grid 2(m) x 4(n)
    uint32_t s3 = (uint32_t)(L & 7), b1 = (uint32_t)((L >> 3) & 1), b2 = (uint32_t)((L >> 4) & 1);
    uint32_t koff = s3 + 8 * b2;

    int n0 = blockIdx.x * BM;
    int b  = n0 >> 10;
    int hw0 = n0 & 1023;
    const float* zb = z + (size_t)b * C_DIM * HW + hw0;

    // --- issue W chunks 0,1 immediately (overlap with A staging) ---
    auto issue_chunk = [&](int g) {
        int kc = g & 3;
        int e0t = (g >> 2) * BM;
        uint32_t buf = W_OFF + (uint32_t)(g % 3) * CHUNK_BYTES;
        #pragma unroll
        for (int i = 0; i < 8; i++) {
            int u = tid + (i << 8);             // 0..2047 16B-units
            int n = u >> 4, c = u & 15;
            uint32_t dst = SB + buf + (uint32_t)n * 256
                         + (((uint32_t)c ^ (uint32_t)(n & 7)) << 4);
            cp16(dst, &g_Wb[(size_t)(e0t + n) * KW + kc * 128 + c * 8]);
        }
        CP_COMMIT();
    };
    issue_chunk(0);
    issue_chunk(1);

    // --- stage A: z tile -> bf16 hi/lo, k-major [k][128], swizzled ---
    #pragma unroll 4
    for (int i = 0; i < 32; i++) {
        int u = tid + (i << 8);
        int k = u >> 5;
        int m4 = (u & 31) << 2;
        float4 v = *reinterpret_cast<const float4*>(zb + (size_t)k * HW + m4);
        __nv_bfloat16 h0 = __float2bfloat16_rn(v.x), h1 = __float2bfloat16_rn(v.y);
        __nv_bfloat16 h2 = __float2bfloat16_rn(v.z), h3 = __float2bfloat16_rn(v.w);
        __nv_bfloat16 l0 = __float2bfloat16_rn(v.x - __bfloat162float(h0));
        __nv_bfloat16 l1 = __float2bfloat16_rn(v.y - __bfloat162float(h1));
        __nv_bfloat16 l2 = __float2bfloat16_rn(v.z - __bfloat162float(h2));
        __nv_bfloat16 l3 = __float2bfloat16_rn(v.w - __bfloat162float(h3));
        uint2 hv, lv;
        hv.x = (uint32_t)__bfloat16_as_ushort(h0) | ((uint32_t)__bfloat16_as_ushort(h1) << 16);
        hv.y = (uint32_t)__bfloat16_as_ushort(h2) | ((uint32_t)__bfloat16_as_ushort(h3) << 16);
        lv.x = (uint32_t)__bfloat16_as_ushort(l0) | ((uint32_t)__bfloat16_as_ushort(l1) << 16);
        lv.y = (uint32_t)__bfloat16_as_ushort(l2) | ((uint32_t)__bfloat16_as_ushort(l3) << 16);
        uint32_t c = (uint32_t)(m4 >> 3);
        uint32_t off = (uint32_t)k * 256 + ((c ^ (uint32_t)(k & 7)) << 4) + ((m4 & 7) << 1);
        *reinterpret_cast<uint2*>(smem + A_HI + off) = hv;
        *reinterpret_cast<uint2*>(smem + A_LO + off) = lv;
    }

    // --- per-thread row bookkeeping ---
    int   rloc[8];
    float Arow[8], bestv[8];
    int   besti[8];
    #pragma unroll
    for (int mt = 0; mt < 4; mt++)
        #pragma unroll
        for (int p = 0; p < 2; p++) {
            int q = mt * 2 + p;
            rloc[q] = mw * 64 + mt * 16 + (L >> 2) + 8 * p;
            Arow[q] = g_znorm[n0 + rloc[q]];
            bestv[q] = 3.4e38f; besti[q] = 0;
        }

    // --- ldmatrix lane offsets ---
    uint32_t aOff[4];
    #pragma unroll
    for (int mt = 0; mt < 4; mt++)
        aOff[mt] = koff * 256
                 + ((((uint32_t)(mw * 64 + mt * 16) >> 3) + b1) ^ s3) * 16;
    uint32_t bRow[2];
    #pragma unroll
    for (int np = 0; np < 2; np++)
        bRow[np] = (uint32_t)(nw * 32 + np * 16) * 256 + koff * 256;

    float acc[4][4][4];
    #pragma unroll
    for (int mt = 0; mt < 4; mt++)
        #pragma unroll
        for (int nt = 0; nt < 4; nt++)
            #pragma unroll
            for (int r = 0; r < 4; r++) acc[mt][nt][r] = 0.f;

    __syncthreads();              // A staged (cp.async tracked separately)

    #pragma unroll 1
    for (int g = 0; g < NITER; g++) {
        CP_WAIT1();               // chunk g landed
        __syncthreads();          // also proves buf (g+2)%3 reclaimable
        if (g + 2 < NITER) issue_chunk(g + 2);
        else CP_COMMIT();         // keep group accounting uniform

        int kc = g & 3;
        uint32_t wb = SB + W_OFF + (uint32_t)(g % 3) * CHUNK_BYTES;
        bool hiW = (kc < 2);
        uint32_t abHI = SB + A_HI + (hiW ? kc : (kc - 2)) * 32768;
        uint32_t abLO = SB + A_LO + kc * 32768;          // valid only if hiW

        #pragma unroll
        for (int s = 0; s < 8; s++) {
            uint32_t a[4][4], bb[2][4];
            uint32_t bco = ((((uint32_t)(s * 2) + b1) ^ s3) << 4);
            #pragma unroll
            for (int np = 0; np < 2; np++) ldsm4(bb[np], wb + bRow[np] + bco);
            uint32_t abh = abHI + (uint32_t)s * 4096;
            #pragma unroll
            for (int mt = 0; mt < 4; mt++) ldsm4t(a[mt], abh + aOff[mt]);
            #pragma unroll
            for (int mt = 0; mt < 4; mt++)
                #pragma unroll
                for (int nt = 0; nt < 4; nt++)
                    mma16816(acc[mt][nt], a[mt], &bb[nt >> 1][(nt & 1) * 2]);
            if (hiW) {            // second A pass reusing W fragments
                uint32_t abl = abLO + (uint32_t)s * 4096;
                #pragma unroll
                for (int mt = 0; mt < 4; mt++) ldsm4t(a[mt], abl + aOff[mt]);
                #pragma unroll
                for (int mt = 0; mt < 4; mt++)
                    #pragma unroll
                    for (int nt = 0; nt < 4; nt++)
                        mma16816(acc[mt][nt], a[mt], &bb[nt >> 1][(nt & 1) * 2]);
            }
        }

        if (kc == 3) {
            int e0 = (g >> 2) * BM;
            #pragma unroll
            for (int mt = 0; mt < 4; mt++)
                #pragma unroll
                for (int nt = 0; nt < 4; nt++) {
                    int c0 = e0 + nw * 32 + nt * 8 + 2 * (L & 3);
                    float s0 = fmaf(-2.0f, acc[mt][nt][0], Arow[mt * 2]);
                    float s1 = fmaf(-2.0f, acc[mt][nt][1], Arow[mt * 2]);
                    float s2 = fmaf(-2.0f, acc[mt][nt][2], Arow[mt * 2 + 1]);
                    float s3v = fmaf(-2.0f, acc[mt][nt][3], Arow[mt * 2 + 1]);
                    if (s0 < bestv[mt * 2])      { bestv[mt * 2] = s0;      besti[mt * 2] = c0; }
                    if (s1 < bestv[mt * 2])      { bestv[mt * 2] = s1;      besti[mt * 2] = c0 + 1; }
                    if (s2 < bestv[mt * 2 + 1])  { bestv[mt * 2 + 1] = s2;  besti[mt * 2 + 1] = c0; }
                    if (s3v < bestv[mt * 2 + 1]) { bestv[mt * 2 + 1] = s3v; besti[mt * 2 + 1] = c0 + 1; }
                    acc[mt][nt][0] = 0.f; acc[mt][nt][1] = 0.f;
                    acc[mt][nt][2] = 0.f; acc[mt][nt][3] = 0.f;
                }
        }
    }

    // --- reduce over the 4 lanes sharing each row ---
    #pragma unroll
    for (int q = 0; q < 8; q++) {
        float v = bestv[q]; int id = besti[q];
        #pragma unroll
        for (int o = 1; o <= 2; o <<= 1) {
            float ov = __shfl_xor_sync(0xFFFFFFFFu, v, o);
            int   oi = __shfl_xor_sync(0xFFFFFFFFu, id, o);
            if (ov < v || (ov == v && oi < id)) { v = ov; id = oi; }
        }
        bestv[q] = v; besti[q] = id;
    }
    __syncthreads();              // W ring idle -> reuse as sred
    float2* sred = reinterpret_cast<float2*>(smem + SRED);
    if ((L & 3) == 0) {
        #pragma unroll
        for (int q = 0; q < 8; q++)
            sred[rloc[q] * 4 + nw] = make_float2(bestv[q], __int_as_float(besti[q]));
    }
    __syncthreads();
    if (tid < BM) {
        float bv = 3.4e38f; int bi = 0;
        #pragma unroll
        for (int w = 0; w < 4; w++) {
            float2 v = sred[tid * 4 + w];
            int id = __float_as_int(v.y);
            if (v.x < bv || (v.x == bv && id < bi)) { bv = v.x; bi = id; }
        }
        g_idx[n0 + tid] = bi;
        atomicAdd(&g_hist[bi], 1);
    }
}

// ===========================================================================
// 3) epilogue: row-major W gather, z_q, loss, index; ticket scalars.
//    grid 1024 blocks = (row-tile, channel-quarter); thread = (row, c-sub).
__global__ void k_epilogue(const float* __restrict__ z, const float* __restrict__ W,
                           float* __restrict__ out) {
    int bid = blockIdx.x;
    int rt = bid >> 2, cq = bid & 3;
    int n0 = rt * BM;
    int b  = n0 >> 10;
    int hw0 = n0 & 1023;
    int tid = threadIdx.x;
    int r = tid & 127;
    int csub = tid >> 7;                        // 0/1
    int cbase = cq * 64 + csub * 32;            // 32 channels per thread

    int id = g_idx[n0 + r];
    if (cq == 0 && tid < BM) out[ZQ_ELEMS + 1 + n0 + tid] = (float)g_idx[n0 + tid];

    const float* wrow = W + (size_t)id * C_DIM + cbase;
    const float* zrow = z + (size_t)b * C_DIM * HW + (size_t)cbase * HW + hw0 + r;
    float* orow = out + (size_t)b * C_DIM * HW + (size_t)cbase * HW + hw0 + r;
    float lsum = 0.f;
    #pragma unroll
    for (int c4 = 0; c4 < 8; c4++) {
        float4 wv = *reinterpret_cast<const float4*>(wrow + c4 * 4);
        float z0 = zrow[(size_t)(c4 * 4 + 0) * HW];
        float z1 = zrow[(size_t)(c4 * 4 + 1) * HW];
        float z2 = zrow[(size_t)(c4 * 4 + 2) * HW];
        float z3 = zrow[(size_t)(c4 * 4 + 3) * HW];
        orow[(size_t)(c4 * 4 + 0) * HW] = wv.x;
        orow[(size_t)(c4 * 4 + 1) * HW] = wv.y;
        orow[(size_t)(c4 * 4 + 2) * HW] = wv.z;
        orow[(size_t)(c4 * 4 + 3) * HW] = wv.w;
        float d0 = wv.x - z0, d1 = wv.y - z1, d2 = wv.z - z2, d3 = wv.w - z3;
        lsum += d0 * d0 + d1 * d1 + d2 * d2 + d3 * d3;
    }

    __shared__ float red[256];
    red[tid] = lsum;
    __syncthreads();
    for (int s = 128; s; s >>= 1) { if (tid < s) red[tid] += red[tid + s]; __syncthreads(); }

    __shared__ unsigned s_ticket;
    if (tid == 0) {
        atomicAdd(&g_loss, (double)red[0]);
        __threadfence();
        s_ticket = atomicAdd(&g_done, 1u);
    }
    __syncthreads();
    if (s_ticket == (unsigned)(EPI_BLOCKS - 1)) {        // last block: scalars
        __threadfence();
        float s = 0.f;
        for (int i = tid; i < N_E; i += 256) {
            float e = (float)g_hist[i] * (1.0f / (float)N_ROWS);
            s += e * logf(e + 1e-10f);
        }
        red[tid] = s;
        __syncthreads();
        for (int st = 128; st; st >>= 1) { if (tid < st) red[tid] += red[tid + st]; __syncthreads(); }
        if (tid == 0) {
            out[ZQ_ELEMS] = 1.25f * (float)(g_loss / (double)ZQ_ELEMS);
            out[ZQ_ELEMS + 1 + N_ROWS] = expf(-red[0]);
        }
    }
}

// ===========================================================================
extern "C" void kernel_launch(void* const* d_in, const int* in_sizes, int n_in,
                              void* d_out, int out_size) {
    const float* z = (const float*)d_in[0];
    const float* W = (const float*)d_in[1];
    float* out = (float*)d_out;

    cudaFuncSetAttribute(k_argmin_mma, cudaFuncAttributeMaxDynamicSharedMemorySize, SMEM_BYTES);

    k_prep<<<PREP_BLOCKS, 256>>>(W, z);                         // launch 1
    k_argmin_mma<<<NRT, 256, SMEM_BYTES>>>(z);                  // launch 2
    k_epilogue<<<EPI_BLOCKS, 256>>>(z, W, out);                 // launch 3
}

// round 15
// speedup vs baseline: 1.0078x; 1.0078x over previous
#include <cuda_runtime.h>
#include <cuda_bf16.h>
#include <math.h>
#include <stdint.h>

#define N_E     8192
#define C_DIM   256
#define BATCH   32
#define HW      1024
#define N_ROWS  (BATCH * HW)            // 32768
#define ZQ_ELEMS (BATCH * C_DIM * HW)   // 8388608

#define BM      128                     // rows per CTA
#define KW      512                     // W row: [hi(256) | lo(256)]
#define NETILE  64                      // e-tiles of 128 codes
#define NITER   (NETILE * 4)            // 256 chunk iterations
#define NRT     (N_ROWS / BM)           // 256 row tiles

// smem offsets (dynamic)
#define A_HI   0                        // [256 k][128 m] bf16 swizzled (64KB)
#define A_LO   65536                    // (64KB)
#define W_OFF  131072                   // 3-stage ring of 32KB chunks
#define CHUNK_BYTES 32768
#define SRED   131072                   // alias of W ring (post-GEMM)
#define SMEM_BYTES (131072 + 3 * CHUNK_BYTES)   // 229376

// prep kernel block ranges — znorm FIRST (long-pole latency blocks start
// earliest and overlap the wprep bulk), then wprep, then zero.
#define PREP_ZNORM_BLOCKS (N_ROWS / 256)        // 128
#define PREP_WPREP_BLOCKS 2048
#define PREP_ZERO_BLOCKS  (N_E / 256)           // 32
#define PREP_BLOCKS (PREP_ZNORM_BLOCKS + PREP_WPREP_BLOCKS + PREP_ZERO_BLOCKS)

// ---- scratch (no allocations allowed) ----
__device__ __align__(16) __nv_bfloat16 g_Wb[N_E * KW];    // [e][hi|lo]  8.4MB
__device__ float  g_znorm[N_ROWS];
__device__ int    g_idx[N_ROWS];
__device__ int    g_hist[N_E];
__device__ double g_loss;
__device__ unsigned g_done;

// =========================== helpers ===================================
__device__ __forceinline__ uint32_t smem_u32(const void* p) {
    uint32_t a;
    asm("{ .reg .u64 t; cvta.to.shared.u64 t, %1; cvt.u32.u64 %0, t; }" : "=r"(a) : "l"(p));
    return a;
}
__device__ __forceinline__ void ldsm4(uint32_t* r, uint32_t addr) {
    asm volatile("ldmatrix.sync.aligned.m8n8.x4.shared.b16 {%0,%1,%2,%3}, [%4];"
                 : "=r"(r[0]), "=r"(r[1]), "=r"(r[2]), "=r"(r[3]) : "r"(addr));
}
__device__ __forceinline__ void ldsm4t(uint32_t* r, uint32_t addr) {
    asm volatile("ldmatrix.sync.aligned.m8n8.x4.trans.shared.b16 {%0,%1,%2,%3}, [%4];"
                 : "=r"(r[0]), "=r"(r[1]), "=r"(r[2]), "=r"(r[3]) : "r"(addr));
}
__device__ __forceinline__ void mma16816(float* d, const uint32_t* a, const uint32_t* b) {
    asm volatile("mma.sync.aligned.m16n8k16.row.col.f32.bf16.bf16.f32 "
                 "{%0,%1,%2,%3}, {%4,%5,%6,%7}, {%8,%9}, {%0,%1,%2,%3};"
                 : "+f"(d[0]), "+f"(d[1]), "+f"(d[2]), "+f"(d[3])
                 : "r"(a[0]), "r"(a[1]), "r"(a[2]), "r"(a[3]), "r"(b[0]), "r"(b[1]));
}
__device__ __forceinline__ void cp16(uint32_t dst, const void* src) {
    asm volatile("cp.async.cg.shared.global [%0], [%1], 16;" :: "r"(dst), "l"(src));
}
#define CP_COMMIT() asm volatile("cp.async.commit_group;" ::: "memory")
#define CP_WAIT1()  asm volatile("cp.async.wait_group 1;"  ::: "memory")

// ===========================================================================
// 1) fused prep: znorm, W hi/lo split, zero.  All independent block ranges.
// ===========================================================================
__global__ void k_prep(const float* __restrict__ W, const float* __restrict__ z) {
    int bid = blockIdx.x;
    int tid = threadIdx.x;
    if (bid < PREP_ZNORM_BLOCKS) {
        // |z_n|^2 — identical accumulation order since R2 (sets score bins)
        int n = bid * 256 + tid;
        int b = n >> 10, hw = n & 1023;
        const float* p = z + (size_t)b * C_DIM * HW + hw;
        float s = 0.f;
        #pragma unroll 8
        for (int c = 0; c < C_DIM; c++) { float v = p[(size_t)c * HW]; s += v * v; }
        g_znorm[n] = s;
    } else if (bid < PREP_ZNORM_BLOCKS + PREP_WPREP_BLOCKS) {
        int wb = bid - PREP_ZNORM_BLOCKS;
        int e0 = (wb & 255) * 32, k0 = (wb >> 8) * 32;
        int tx = tid & 31, ty = tid >> 5;
        #pragma unroll
        for (int j = 0; j < 4; j++) {
            int e = e0 + ty + 8 * j;
            int k = k0 + tx;
            float w = W[(size_t)e * C_DIM + k];
            __nv_bfloat16 hi = __float2bfloat16_rn(w);
            __nv_bfloat16 lo = __float2bfloat16_rn(w - __bfloat162float(hi));
            size_t base = (size_t)e * KW;
            g_Wb[base + k]       = hi;
            g_Wb[base + 256 + k] = lo;
        }
    } else {
        int i = (bid - PREP_ZNORM_BLOCKS - PREP_WPREP_BLOCKS) * 256 + tid;
        if (i < N_E) g_hist[i] = 0;
        if (i == 0)  { g_loss = 0.0; g_done = 0u; }
    }
}

// ===========================================================================
// 2) main: bf16 HMMA argmin — BYTE-IDENTICAL to R13 (grid 256, 256 thr).
//    score = fl(|z|^2 - 2*(z.w));  dot = hi.hi + lo.hi + hi.lo  (3 passes)
// ===========================================================================
__global__ __launch_bounds__(256, 1)
void k_argmin_mma(const float* __restrict__ z) {
    extern __shared__ char smem[];
    const uint32_t SB = smem_u32(smem);
    int tid = threadIdx.x;
    int L = tid & 31, wid = tid >> 5;
    int mw = wid >> 2, nw = wid & 3;            // warp grid 2(m) x 4(n)
    uint32_t s3 = (uint32_t)(L & 7), b1 = (uint32_t)((L >> 3) & 1), b2 = (uint32_t)((L >> 4) & 1);
    uint32_t koff = s3 + 8 * b2;

    int n0 = blockIdx.x * BM;
    int b  = n0 >> 10;
    int hw0 = n0 & 1023;
    const float* zb = z + (size_t)b * C_DIM * HW + hw0;

    // --- issue W chunks 0,1 immediately (overlap with A staging) ---
    auto issue_chunk = [&](int g) {
        int kc = g & 3;
        int e0t = (g >> 2) * BM;
        uint32_t buf = W_OFF + (uint32_t)(g % 3) * CHUNK_BYTES;
        #pragma unroll
        for (int i = 0; i < 8; i++) {
            int u = tid + (i << 8);             // 0..2047 16B-units
            int n = u >> 4, c = u & 15;
            uint32_t dst = SB + buf + (uint32_t)n * 256
                         + (((uint32_t)c ^ (uint32_t)(n & 7)) << 4);
            cp16(dst, &g_Wb[(size_t)(e0t + n) * KW + kc * 128 + c * 8]);
        }
        CP_COMMIT();
    };
    issue_chunk(0);
    issue_chunk(1);

    // --- stage A: z tile -> bf16 hi/lo, k-major [k][128], swizzled ---
    #pragma unroll 4
    for (int i = 0; i < 32; i++) {
        int u = tid + (i << 8);
        int k = u >> 5;
        int m4 = (u & 31) << 2;
        float4 v = *reinterpret_cast<const float4*>(zb + (size_t)k * HW + m4);
        __nv_bfloat16 h0 = __float2bfloat16_rn(v.x), h1 = __float2bfloat16_rn(v.y);
        __nv_bfloat16 h2 = __float2bfloat16_rn(v.z), h3 = __float2bfloat16_rn(v.w);
        __nv_bfloat16 l0 = __float2bfloat16_rn(v.x - __bfloat162float(h0));
        __nv_bfloat16 l1 = __float2bfloat16_rn(v.y - __bfloat162float(h1));
        __nv_bfloat16 l2 = __float2bfloat16_rn(v.z - __bfloat162float(h2));
        __nv_bfloat16 l3 = __float2bfloat16_rn(v.w - __bfloat162float(h3));
        uint2 hv, lv;
        hv.x = (uint32_t)__bfloat16_as_ushort(h0) | ((uint32_t)__bfloat16_as_ushort(h1) << 16);
        hv.y = (uint32_t)__bfloat16_as_ushort(h2) | ((uint32_t)__bfloat16_as_ushort(h3) << 16);
        lv.x = (uint32_t)__bfloat16_as_ushort(l0) | ((uint32_t)__bfloat16_as_ushort(l1) << 16);
        lv.y = (uint32_t)__bfloat16_as_ushort(l2) | ((uint32_t)__bfloat16_as_ushort(l3) << 16);
        uint32_t c = (uint32_t)(m4 >> 3);
        uint32_t off = (uint32_t)k * 256 + ((c ^ (uint32_t)(k & 7)) << 4) + ((m4 & 7) << 1);
        *reinterpret_cast<uint2*>(smem + A_HI + off) = hv;
        *reinterpret_cast<uint2*>(smem + A_LO + off) = lv;
    }

    // --- per-thread row bookkeeping ---
    int   rloc[8];
    float Arow[8], bestv[8];
    int   besti[8];
    #pragma unroll
    for (int mt = 0; mt < 4; mt++)
        #pragma unroll
        for (int p = 0; p < 2; p++) {
            int q = mt * 2 + p;
            rloc[q] = mw * 64 + mt * 16 + (L >> 2) + 8 * p;
            Arow[q] = g_znorm[n0 + rloc[q]];
            bestv[q] = 3.4e38f; besti[q] = 0;
        }

    // --- ldmatrix lane offsets ---
    uint32_t aOff[4];
    #pragma unroll
    for (int mt = 0; mt < 4; mt++)
        aOff[mt] = koff * 256
                 + ((((uint32_t)(mw * 64 + mt * 16) >> 3) + b1) ^ s3) * 16;
    uint32_t bRow[2];
    #pragma unroll
    for (int np = 0; np < 2; np++)
        bRow[np] = (uint32_t)(nw * 32 + np * 16) * 256 + koff * 256;

    float acc[4][4][4];
    #pragma unroll
    for (int mt = 0; mt < 4; mt++)
        #pragma unroll
        for (int nt = 0; nt < 4; nt++)
            #pragma unroll
            for (int r = 0; r < 4; r++) acc[mt][nt][r] = 0.f;

    __syncthreads();              // A staged (cp.async tracked separately)

    #pragma unroll 1
    for (int g = 0; g < NITER; g++) {
        CP_WAIT1();               // chunk g landed
        __syncthreads();          // also proves buf (g+2)%3 reclaimable
        if (g + 2 < NITER) issue_chunk(g + 2);
        else CP_COMMIT();         // keep group accounting uniform

        int kc = g & 3;
        uint32_t wb = SB + W_OFF + (uint32_t)(g % 3) * CHUNK_BYTES;
        bool hiW = (kc < 2);
        uint32_t abHI = SB + A_HI + (hiW ? kc : (kc - 2)) * 32768;
        uint32_t abLO = SB + A_LO + kc * 32768;          // valid only if hiW

        #pragma unroll
        for (int s = 0; s < 8; s++) {
            uint32_t a[4][4], bb[2][4];
            uint32_t bco = ((((uint32_t)(s * 2) + b1) ^ s3) << 4);
            #pragma unroll
            for (int np = 0; np < 2; np++) ldsm4(bb[np], wb + bRow[np] + bco);
            uint32_t abh = abHI + (uint32_t)s * 4096;
            #pragma unroll
            for (int mt = 0; mt < 4; mt++) ldsm4t(a[mt], abh + aOff[mt]);
            #pragma unroll
            for (int mt = 0; mt < 4; mt++)
                #pragma unroll
                for (int nt = 0; nt < 4; nt++)
                    mma16816(acc[mt][nt], a[mt], &bb[nt >> 1][(nt & 1) * 2]);
            if (hiW) {            // second A pass reusing W fragments
                uint32_t abl = abLO + (uint32_t)s * 4096;
                #pragma unroll
                for (int mt = 0; mt < 4; mt++) ldsm4t(a[mt], abl + aOff[mt]);
                #pragma unroll
                for (int mt = 0; mt < 4; mt++)
                    #pragma unroll
                    for (int nt = 0; nt < 4; nt++)
                        mma16816(acc[mt][nt], a[mt], &bb[nt >> 1][(nt & 1) * 2]);
            }
        }

        if (kc == 3) {
            int e0 = (g >> 2) * BM;
            #pragma unroll
            for (int mt = 0; mt < 4; mt++)
                #pragma unroll
                for (int nt = 0; nt < 4; nt++) {
                    int c0 = e0 + nw * 32 + nt * 8 + 2 * (L & 3);
                    float s0 = fmaf(-2.0f, acc[mt][nt][0], Arow[mt * 2]);
                    float s1 = fmaf(-2.0f, acc[mt][nt][1], Arow[mt * 2]);
                    float s2 = fmaf(-2.0f, acc[mt][nt][2], Arow[mt * 2 + 1]);
                    float s3v = fmaf(-2.0f, acc[mt][nt][3], Arow[mt * 2 + 1]);
                    if (s0 < bestv[mt * 2])      { bestv[mt * 2] = s0;      besti[mt * 2] = c0; }
                    if (s1 < bestv[mt * 2])      { bestv[mt * 2] = s1;      besti[mt * 2] = c0 + 1; }
                    if (s2 < bestv[mt * 2 + 1])  { bestv[mt * 2 + 1] = s2;  besti[mt * 2 + 1] = c0; }
                    if (s3v < bestv[mt * 2 + 1]) { bestv[mt * 2 + 1] = s3v; besti[mt * 2 + 1] = c0 + 1; }
                    acc[mt][nt][0] = 0.f; acc[mt][nt][1] = 0.f;
                    acc[mt][nt][2] = 0.f; acc[mt][nt][3] = 0.f;
                }
        }
    }

    // --- reduce over the 4 lanes sharing each row ---
    #pragma unroll
    for (int q = 0; q < 8; q++) {
        float v = bestv[q]; int id = besti[q];
        #pragma unroll
        for (int o = 1; o <= 2; o <<= 1) {
            float ov = __shfl_xor_sync(0xFFFFFFFFu, v, o);
            int   oi = __shfl_xor_sync(0xFFFFFFFFu, id, o);
            if (ov < v || (ov == v && oi < id)) { v = ov; id = oi; }
        }
        bestv[q] = v; besti[q] = id;
    }
    __syncthreads();              // W ring idle -> reuse as sred
    float2* sred = reinterpret_cast<float2*>(smem + SRED);
    if ((L & 3) == 0) {
        #pragma unroll
        for (int q = 0; q < 8; q++)
            sred[rloc[q] * 4 + nw] = make_float2(bestv[q], __int_as_float(besti[q]));
    }
    __syncthreads();
    if (tid < BM) {
        float bv = 3.4e38f; int bi = 0;
        #pragma unroll
        for (int w = 0; w < 4; w++) {
            float2 v = sred[tid * 4 + w];
            int id = __float_as_int(v.y);
            if (v.x < bv || (v.x == bv && id < bi)) { bv = v.x; bi = id; }
        }
        g_idx[n0 + tid] = bi;
        atomicAdd(&g_hist[bi], 1);
    }
}

// ===========================================================================
// 3) epilogue (R13 version): row-major W gather, z_q, loss, index; ticket.
//    grid 256 blocks (one per row-tile), thread = (row, c-half).
__global__ void k_epilogue(const float* __restrict__ z, const float* __restrict__ W,
                           float* __restrict__ out) {
    int rt = blockIdx.x;
    int n0 = rt * BM;
    int b  = n0 >> 10;
    int hw0 = n0 & 1023;
    int tid = threadIdx.x;
    int r = tid & 127;
    int chalf = tid >> 7;                       // 0/1 -> c in [chalf*128, +128)

    int id = g_idx[n0 + r];
    if (tid < BM) out[ZQ_ELEMS + 1 + n0 + tid] = (float)g_idx[n0 + tid];

    const float* wrow = W + (size_t)id * C_DIM + chalf * 128;
    const float* zrow = z + (size_t)b * C_DIM * HW + (size_t)(chalf * 128) * HW + hw0 + r;
    float* orow = out + (size_t)b * C_DIM * HW + (size_t)(chalf * 128) * HW + hw0 + r;
    float lsum = 0.f;
    #pragma unroll 4
    for (int c4 = 0; c4 < 32; c4++) {
        float4 wv = *reinterpret_cast<const float4*>(wrow + c4 * 4);
        float z0 = zrow[(size_t)(c4 * 4 + 0) * HW];
        float z1 = zrow[(size_t)(c4 * 4 + 1) * HW];
        float z2 = zrow[(size_t)(c4 * 4 + 2) * HW];
        float z3 = zrow[(size_t)(c4 * 4 + 3) * HW];
        orow[(size_t)(c4 * 4 + 0) * HW] = wv.x;
        orow[(size_t)(c4 * 4 + 1) * HW] = wv.y;
        orow[(size_t)(c4 * 4 + 2) * HW] = wv.z;
        orow[(size_t)(c4 * 4 + 3) * HW] = wv.w;
        float d0 = wv.x - z0, d1 = wv.y - z1, d2 = wv.z - z2, d3 = wv.w - z3;
        lsum += d0 * d0 + d1 * d1 + d2 * d2 + d3 * d3;
    }

    __shared__ float red[256];
    red[tid] = lsum;
    __syncthreads();
    for (int s = 128; s; s >>= 1) { if (tid < s) red[tid] += red[tid + s]; __syncthreads(); }

    __shared__ unsigned s_ticket;
    if (tid == 0) {
        atomicAdd(&g_loss, (double)red[0]);
        __threadfence();
        s_ticket = atomicAdd(&g_done, 1u);
    }
    __syncthreads();
    if (s_ticket == (unsigned)(NRT - 1)) {      // last block: final scalars
        __threadfence();
        float s = 0.f;
        for (int i = tid; i < N_E; i += 256) {
            float e = (float)g_hist[i] * (1.0f / (float)N_ROWS);
            s += e * logf(e + 1e-10f);
        }
        red[tid] = s;
        __syncthreads();
        for (int st = 128; st; st >>= 1) { if (tid < st) red[tid] += red[tid + st]; __syncthreads(); }
        if (tid == 0) {
            out[ZQ_ELEMS] = 1.25f * (float)(g_loss / (double)ZQ_ELEMS);
            out[ZQ_ELEMS + 1 + N_ROWS] = expf(-red[0]);
        }
    }
}

// ===========================================================================
extern "C" void kernel_launch(void* const* d_in, const int* in_sizes, int n_in,
                              void* d_out, int out_size) {
    const float* z = (const float*)d_in[0];
    const float* W = (const float*)d_in[1];
    float* out = (float*)d_out;

    cudaFuncSetAttribute(k_argmin_mma, cudaFuncAttributeMaxDynamicSharedMemorySize, SMEM_BYTES);

    k_prep<<<PREP_BLOCKS, 256>>>(W, z);                         // launch 1
    k_argmin_mma<<<NRT, 256, SMEM_BYTES>>>(z);                  // launch 2
    k_epilogue<<<NRT, 256>>>(z, W, out);                        // launch 3
}